// round 13
// baseline (speedup 1.0000x reference)
#include <cuda_runtime.h>
#include <cuda_fp16.h>
#include <cstdint>

// RNN-T joint network, ONE launch (grid=256, all co-resident @ occ 2):
//   0a: ALL blocks convert pred + W_pred (fp32->fp16), barrier c1 (256).
//   then: bids 0..63 run pred GEMM 64x128 -> g_pred + flag   (overlapped
//         with) bids 64..255 converting enc + W_enc; barrier c2 (192).
//   all: enc GEMM 64x128 -> smem; wait 1 pred flag (normally pre-set);
//        drain 2MB output brick with coalesced stores.
//   R13: drain uses DEFAULT (.wb) stores instead of .cs — output is
//        write-only since R7; let L2 write-coalesce into full-line bursts.
//   end: completion counter; block 0 resets flags/counters (graph replay).

#define VOCAB 2048
#define KC    512
#define NB    4
#define NT    256
#define NU    64
#define GRID  256
#define NDUAL 64

// -------- scratch (device globals; no allocations allowed) --------
__device__ __half g_Ac[1280 * KC];      // enc rows 0..1023, pred rows 1024..1279
__device__ __half g_Be[VOCAB * KC];
__device__ __half g_Bp[VOCAB * KC];
__device__ float  g_pred[256 * VOCAB];
__device__ int    g_flags[64];          // pred tile (pb, n): pb*16 + n
__device__ int    g_c1;                 // 0a barrier (target 256)
__device__ int    g_c2;                 // 0b barrier (target 192)
__device__ int    g_done;               // completion counter (for reset)

// ---------------------------------------------------------------------------
// helpers
// ---------------------------------------------------------------------------
#define BK     64
#define STAGES 3
#define A_ST   8192                   // 64 rows * 128B
#define B_ST   16384                  // 128 rows * 128B
#define ST_SZ  (A_ST + B_ST)          // 24KB per stage
#define DSMEM  (STAGES * ST_SZ)       // 72KB (drain needs 67.6KB <= this)
#define PSTR   132                    // padded fp32 row stride for drain tiles

__device__ __forceinline__ uint32_t s2u(const void* p) {
    return (uint32_t)__cvta_generic_to_shared(p);
}
#define CPA16(s, g) asm volatile("cp.async.cg.shared.global [%0], [%1], 16;" :: "r"(s), "l"(g))
#define LDSM4(r0,r1,r2,r3,a) asm volatile( \
    "ldmatrix.sync.aligned.m8n8.x4.shared.b16 {%0,%1,%2,%3}, [%4];" \
    : "=r"(r0),"=r"(r1),"=r"(r2),"=r"(r3) : "r"(a))
#define MMA16816(c,a0,a1,a2,a3,b0,b1) asm volatile( \
    "mma.sync.aligned.m16n8k16.row.col.f32.f16.f16.f32 " \
    "{%0,%1,%2,%3},{%4,%5,%6,%7},{%8,%9},{%0,%1,%2,%3};" \
    : "+f"(c[0]),"+f"(c[1]),"+f"(c[2]),"+f"(c[3]) \
    : "r"(a0),"r"(a1),"r"(a2),"r"(a3),"r"(b0),"r"(b1))

__device__ __forceinline__ uint32_t swz(uint32_t row, uint32_t cb) {
    return row * 128 + (cb ^ ((row & 7) * 16));
}
__device__ __forceinline__ void std4(float4* p, float4 v) {
    asm volatile("st.global.v4.f32 [%0], {%1,%2,%3,%4};"
                 :: "l"(p), "f"(v.x), "f"(v.y), "f"(v.z), "f"(v.w));
}
__device__ __forceinline__ void wait_flag(const int* f) {
    int v;
    while (true) {
        asm volatile("ld.acquire.gpu.global.b32 %0, [%1];" : "=r"(v) : "l"(f));
        if (v) break;
        __nanosleep(128);
    }
}
__device__ __forceinline__ void wait_cnt(const int* f, int target) {
    int v;
    while (true) {
        asm volatile("ld.acquire.gpu.global.b32 %0, [%1];" : "=r"(v) : "l"(f));
        if (v == target) break;
        __nanosleep(64);
    }
}

// ---------------------------------------------------------------------------
// one 64x128 fp16 GEMM tile, K=512 (proven R10/R11 mainloop)
// ---------------------------------------------------------------------------
__device__ __forceinline__ void gemm_tile(uint32_t sb, int tid, int lane,
                                          int warp_m, int warp_n,
                                          const __half* __restrict__ gA,
                                          const __half* __restrict__ gB,
                                          float (&c)[2][4][4]) {
    #pragma unroll
    for (int i = 0; i < 2; i++)
        #pragma unroll
        for (int j = 0; j < 4; j++)
            #pragma unroll
            for (int e2 = 0; e2 < 4; e2++) c[i][j][e2] = 0.f;

    const int ra0 = tid >> 3,         ja0 = (tid & 7) * 16;
    const int ra1 = (tid + 256) >> 3;
    const uint32_t sA0 = swz(ra0, ja0), sA1 = swz(ra1, ja0);
    int      rb[4], jb[4];
    uint32_t sB[4];
    #pragma unroll
    for (int i = 0; i < 4; i++) {
        int cidx = tid + i * 256;
        rb[i] = cidx >> 3; jb[i] = (cidx & 7) * 16;
        sB[i] = swz(rb[i], jb[i]);
    }

    const int rowA = warp_m * 32 + (lane & 15);
    const uint32_t uA = swz(rowA, (lane >> 4) * 16);
    const int rowB = warp_n * 32 + ((lane >> 4) & 1) * 8 + (lane & 7);
    const uint32_t uB = swz(rowB, ((lane >> 3) & 1) * 16);

    auto fill = [&](int s, int koff) {
        const uint32_t ab = sb + s * ST_SZ;
        const uint32_t bb = ab + A_ST;
        CPA16(ab + sA0, gA + (size_t)ra0 * KC + koff + ja0 / 2);
        CPA16(ab + sA1, gA + (size_t)ra1 * KC + koff + ja0 / 2);
        #pragma unroll
        for (int i = 0; i < 4; i++)
            CPA16(bb + sB[i], gB + (size_t)rb[i] * KC + koff + jb[i] / 2);
        asm volatile("cp.async.commit_group;");
    };

    fill(0, 0);
    fill(1, BK);

    const int NKT = KC / BK;   // 8
    int s = 0;
    for (int kt = 0; kt < NKT; kt++) {
        if (kt < NKT - 1) asm volatile("cp.async.wait_group 1;");
        else              asm volatile("cp.async.wait_group 0;");
        __syncthreads();

        if (kt + 2 < NKT) {
            int sn = s + 2; if (sn >= STAGES) sn -= STAGES;
            fill(sn, (kt + 2) * BK);
        }

        const uint32_t abase = sb + s * ST_SZ + uA;
        const uint32_t bbase = sb + s * ST_SZ + A_ST + uB;
        #pragma unroll
        for (int kk = 0; kk < 4; kk++) {
            uint32_t a[2][4], bfr[2][4];
            #pragma unroll
            for (int mi = 0; mi < 2; mi++)
                LDSM4(a[mi][0], a[mi][1], a[mi][2], a[mi][3],
                      (abase + mi * 2048) ^ (kk << 5));
            #pragma unroll
            for (int nb = 0; nb < 2; nb++)
                LDSM4(bfr[nb][0], bfr[nb][1], bfr[nb][2], bfr[nb][3],
                      (bbase + nb * 2048) ^ (kk << 5));
            #pragma unroll
            for (int mi = 0; mi < 2; mi++) {
                MMA16816(c[mi][0], a[mi][0], a[mi][1], a[mi][2], a[mi][3], bfr[0][0], bfr[0][1]);
                MMA16816(c[mi][1], a[mi][0], a[mi][1], a[mi][2], a[mi][3], bfr[0][2], bfr[0][3]);
                MMA16816(c[mi][2], a[mi][0], a[mi][1], a[mi][2], a[mi][3], bfr[1][0], bfr[1][1]);
                MMA16816(c[mi][3], a[mi][0], a[mi][1], a[mi][2], a[mi][3], bfr[1][2], bfr[1][3]);
            }
        }
        if (++s >= STAGES) s -= STAGES;
    }
    __syncthreads();   // smem free for next use
}

// ---------------------------------------------------------------------------
// Fused kernel: split-phase convert, pred GEMM overlapped with enc convert.
// ---------------------------------------------------------------------------
__global__ __launch_bounds__(256, 2)
void fused_kernel(const float* __restrict__ enc_in,
                  const float* __restrict__ pred_in,
                  const float* __restrict__ W,
                  const float* __restrict__ bias,
                  float* __restrict__ out) {
    extern __shared__ __align__(1024) char smem[];
    const uint32_t sb = s2u(smem);
    const int bid = blockIdx.x;
    const int tid = threadIdx.x;
    const int lane = tid & 31;
    const int wid  = tid >> 5;
    const int warp_m = wid & 1;     // 32 M rows
    const int warp_n = wid >> 1;    // 32 N cols

    // ---------- phase 0a: convert pred + W_pred (all 256 blocks) ----------
    {
        const int base = bid * 256 + tid;        // 0..65535
        // pred: 65536 float2 pairs (1/thread)
        {
            float2 x = ((const float2*)pred_in)[base];
            int mm = 1024 + (base >> 8), k2 = (base & 255) * 2;
            *(__half2*)(g_Ac + (size_t)mm * KC + k2) = __floats2half2_rn(x.x, x.y);
        }
        // W_pred half: 524288 pairs (8/thread). W row = 512 pairs; Bp = pairs 256..511.
        #pragma unroll
        for (int j = 0; j < 8; j++) {
            int q = base + j * 65536;            // 0..524287
            int v = q >> 8, kp = q & 255;
            float2 x = ((const float2*)W)[(size_t)v * 512 + 256 + kp];
            *(__half2*)(g_Bp + (size_t)v * KC + kp * 2) = __floats2half2_rn(x.x, x.y);
        }
    }
    __threadfence();
    __syncthreads();
    if (tid == 0) atomicAdd(&g_c1, 1);

    const int m = bid >> 4, n = bid & 15;     // enc tile coords
    const int b = m >> 2;
    const int vbase = n * 128;

    float c[2][4][4];
    const int mrow0 = warp_m * 32 + (lane >> 2);
    const int ncol0 = warp_n * 32 + (lane & 3) * 2;

    if (bid < NDUAL) {
        // ---------- dual blocks: pred GEMM (tile pb=m, n), overlapped ----
        if (tid == 0) wait_cnt(&g_c1, GRID);
        __syncthreads();
        gemm_tile(sb, tid, lane, warp_m, warp_n,
                  g_Ac + (size_t)(1024 + m * 64) * KC,
                  g_Bp + (size_t)(n * 128) * KC, c);
        float* C = g_pred + (size_t)(m * 64) * VOCAB + vbase;
        #pragma unroll
        for (int mi = 0; mi < 2; mi++) {
            #pragma unroll
            for (int ni = 0; ni < 4; ni++) {
                float* p0 = &C[(size_t)(mrow0 + mi * 16)     * VOCAB + ncol0 + ni * 8];
                float* p1 = &C[(size_t)(mrow0 + mi * 16 + 8) * VOCAB + ncol0 + ni * 8];
                *(float2*)p0 = make_float2(c[mi][ni][0], c[mi][ni][1]);
                *(float2*)p1 = make_float2(c[mi][ni][2], c[mi][ni][3]);
            }
        }
        __threadfence();
        __syncthreads();
        if (tid == 0) {
            atomicExch(&g_flags[m * 16 + n], 1);
            wait_cnt(&g_c2, GRID - NDUAL);      // enc/Be images ready?
        }
        __syncthreads();
    } else {
        // ---------- other blocks: phase 0b convert enc + W_enc -----------
        const int lid = bid - NDUAL;             // 0..191
        const int base = lid * 256 + tid;
        #pragma unroll
        for (int j = 0; j < 16; j++) {
            int t = base + j * 49152;            // 0..786431
            if (t < 262144) {                    // enc: 1024 rows x 256 pairs
                float2 x = ((const float2*)enc_in)[t];
                int mm = t >> 8, k2 = (t & 255) * 2;
                *(__half2*)(g_Ac + (size_t)mm * KC + k2) = __floats2half2_rn(x.x, x.y);
            } else {                             // W_enc half: pairs 0..255 per row
                int q = t - 262144;              // 0..524287
                int v = q >> 8, kp = q & 255;
                float2 x = ((const float2*)W)[(size_t)v * 512 + kp];
                *(__half2*)(g_Be + (size_t)v * KC + kp * 2) = __floats2half2_rn(x.x, x.y);
            }
        }
        __threadfence();
        __syncthreads();
        if (tid == 0) {
            atomicAdd(&g_c2, 1);
            wait_cnt(&g_c2, GRID - NDUAL);
        }
        __syncthreads();
    }

    // ---------- enc GEMM: tile (m, n) ----------
    gemm_tile(sb, tid, lane, warp_m, warp_n,
              g_Ac + (size_t)(m * 64) * KC,
              g_Be + (size_t)(n * 128) * KC, c);

    // ---------- enc epilogue: frags -> smem, fetch pred tile, drain ------
    float* enc_s  = (float*)smem;          // [64][PSTR]
    float* pred_s = enc_s + 64 * PSTR;     // [64][PSTR]

    #pragma unroll
    for (int mi = 0; mi < 2; mi++) {
        #pragma unroll
        for (int ni = 0; ni < 4; ni++) {
            float* p0 = &enc_s[(mrow0 + mi * 16)     * PSTR + ncol0 + ni * 8];
            float* p1 = &enc_s[(mrow0 + mi * 16 + 8) * PSTR + ncol0 + ni * 8];
            *(float2*)p0 = make_float2(c[mi][ni][0], c[mi][ni][1]);
            *(float2*)p1 = make_float2(c[mi][ni][2], c[mi][ni][3]);
        }
    }

    if (tid == 0) wait_flag(&g_flags[b * 16 + n]);
    __syncthreads();

    // pred tile + bias -> smem: 64u x 128v = 2048 float4, 8/thread
    {
        const float* pg = g_pred + (size_t)(b * NU) * VOCAB + vbase;
        #pragma unroll
        for (int i = 0; i < 8; i++) {
            int e = tid + i * 256;
            int u = e >> 5, cc = e & 31;
            float4 p = *(const float4*)(pg + (size_t)u * VOCAB + cc * 4);
            float4 bv = *(const float4*)(bias + vbase + cc * 4);
            *(float4*)&pred_s[u * PSTR + cc * 4] =
                make_float4(p.x + bv.x, p.y + bv.y, p.z + bv.z, p.w + bv.w);
        }
    }
    __syncthreads();

    // drain: warp w handles t rows [w*8, w*8+8); per (t,u) row a full warp
    // stores 128 contiguous floats (512B, coalesced). Default (.wb) stores.
    const int col   = lane;
    const int tbase = (m & 3) * 64;
    float* ob = out + ((size_t)(b * NT + tbase) * NU) * VOCAB + vbase;

    #pragma unroll
    for (int ti = 0; ti < 8; ti++) {
        const int t = wid * 8 + ti;
        float4 e = *(float4*)&enc_s[t * PSTR + col * 4];
        float4* orow = (float4*)(ob + (size_t)t * NU * VOCAB);
        #pragma unroll 8
        for (int u = 0; u < NU; u++) {
            float4 p = *(float4*)&pred_s[u * PSTR + col * 4];
            std4(&orow[u * (VOCAB / 4) + col],
                 make_float4(e.x + p.x, e.y + p.y, e.z + p.z, e.w + p.w));
        }
    }

    // ---------- completion + reset (graph-replay correctness) ----------
    __syncthreads();
    if (tid == 0) {
        atomicAdd(&g_done, 1);
        if (bid == 0) {
            wait_cnt(&g_done, GRID);
            #pragma unroll
            for (int i = 0; i < 64; i++) g_flags[i] = 0;
            g_c1 = 0;
            g_c2 = 0;
            g_done = 0;
            __threadfence();
        }
    }
}

// ---------------------------------------------------------------------------
extern "C" void kernel_launch(void* const* d_in, const int* in_sizes, int n_in,
                              void* d_out, int out_size) {
    const float* enc  = (const float*)d_in[0];
    const float* pred = (const float*)d_in[1];
    const float* W    = (const float*)d_in[2];
    const float* bias = (const float*)d_in[3];
    float* out = (float*)d_out;

    cudaFuncSetAttribute(fused_kernel,
                         cudaFuncAttributeMaxDynamicSharedMemorySize, DSMEM);

    fused_kernel<<<GRID, 256, DSMEM>>>(enc, pred, W, bias, out);
}

// round 14
// speedup vs baseline: 1.0102x; 1.0102x over previous
#include <cuda_runtime.h>
#include <cuda_fp16.h>
#include <cstdint>

// RNN-T joint network, ONE launch (grid=256, all co-resident @ occ 2):
//   0a: ALL blocks convert pred + W_pred (fp32->fp16), barrier c1 (256).
//   then: bids 0..63 run pred GEMM 64x128 -> g_pred + flag   (overlapped
//         with) bids 64..255 converting enc + W_enc; barrier c2 (192).
//   all: enc GEMM 64x128 -> smem; wait 1 pred flag (normally pre-set);
//        drain 2MB output brick with coalesced default (.wb) stores.
//   R14: re-bench of R13 (kernel measured 97.3us = modeled write floor;
//        bench total showed anomalous 4.6us harness gap — verifying).
//   end: completion counter; block 0 resets flags/counters (graph replay).

#define VOCAB 2048
#define KC    512
#define NB    4
#define NT    256
#define NU    64
#define GRID  256
#define NDUAL 64

// -------- scratch (device globals; no allocations allowed) --------
__device__ __half g_Ac[1280 * KC];      // enc rows 0..1023, pred rows 1024..1279
__device__ __half g_Be[VOCAB * KC];
__device__ __half g_Bp[VOCAB * KC];
__device__ float  g_pred[256 * VOCAB];
__device__ int    g_flags[64];          // pred tile (pb, n): pb*16 + n
__device__ int    g_c1;                 // 0a barrier (target 256)
__device__ int    g_c2;                 // 0b barrier (target 192)
__device__ int    g_done;               // completion counter (for reset)

// ---------------------------------------------------------------------------
// helpers
// ---------------------------------------------------------------------------
#define BK     64
#define STAGES 3
#define A_ST   8192                   // 64 rows * 128B
#define B_ST   16384                  // 128 rows * 128B
#define ST_SZ  (A_ST + B_ST)          // 24KB per stage
#define DSMEM  (STAGES * ST_SZ)       // 72KB (drain needs 67.6KB <= this)
#define PSTR   132                    // padded fp32 row stride for drain tiles

__device__ __forceinline__ uint32_t s2u(const void* p) {
    return (uint32_t)__cvta_generic_to_shared(p);
}
#define CPA16(s, g) asm volatile("cp.async.cg.shared.global [%0], [%1], 16;" :: "r"(s), "l"(g))
#define LDSM4(r0,r1,r2,r3,a) asm volatile( \
    "ldmatrix.sync.aligned.m8n8.x4.shared.b16 {%0,%1,%2,%3}, [%4];" \
    : "=r"(r0),"=r"(r1),"=r"(r2),"=r"(r3) : "r"(a))
#define MMA16816(c,a0,a1,a2,a3,b0,b1) asm volatile( \
    "mma.sync.aligned.m16n8k16.row.col.f32.f16.f16.f32 " \
    "{%0,%1,%2,%3},{%4,%5,%6,%7},{%8,%9},{%0,%1,%2,%3};" \
    : "+f"(c[0]),"+f"(c[1]),"+f"(c[2]),"+f"(c[3]) \
    : "r"(a0),"r"(a1),"r"(a2),"r"(a3),"r"(b0),"r"(b1))

__device__ __forceinline__ uint32_t swz(uint32_t row, uint32_t cb) {
    return row * 128 + (cb ^ ((row & 7) * 16));
}
__device__ __forceinline__ void std4(float4* p, float4 v) {
    asm volatile("st.global.v4.f32 [%0], {%1,%2,%3,%4};"
                 :: "l"(p), "f"(v.x), "f"(v.y), "f"(v.z), "f"(v.w));
}
__device__ __forceinline__ void wait_flag(const int* f) {
    int v;
    while (true) {
        asm volatile("ld.acquire.gpu.global.b32 %0, [%1];" : "=r"(v) : "l"(f));
        if (v) break;
        __nanosleep(128);
    }
}
__device__ __forceinline__ void wait_cnt(const int* f, int target) {
    int v;
    while (true) {
        asm volatile("ld.acquire.gpu.global.b32 %0, [%1];" : "=r"(v) : "l"(f));
        if (v == target) break;
        __nanosleep(64);
    }
}

// ---------------------------------------------------------------------------
// one 64x128 fp16 GEMM tile, K=512 (proven R10-R13 mainloop)
// ---------------------------------------------------------------------------
__device__ __forceinline__ void gemm_tile(uint32_t sb, int tid, int lane,
                                          int warp_m, int warp_n,
                                          const __half* __restrict__ gA,
                                          const __half* __restrict__ gB,
                                          float (&c)[2][4][4]) {
    #pragma unroll
    for (int i = 0; i < 2; i++)
        #pragma unroll
        for (int j = 0; j < 4; j++)
            #pragma unroll
            for (int e2 = 0; e2 < 4; e2++) c[i][j][e2] = 0.f;

    const int ra0 = tid >> 3,         ja0 = (tid & 7) * 16;
    const int ra1 = (tid + 256) >> 3;
    const uint32_t sA0 = swz(ra0, ja0), sA1 = swz(ra1, ja0);
    int      rb[4], jb[4];
    uint32_t sB[4];
    #pragma unroll
    for (int i = 0; i < 4; i++) {
        int cidx = tid + i * 256;
        rb[i] = cidx >> 3; jb[i] = (cidx & 7) * 16;
        sB[i] = swz(rb[i], jb[i]);
    }

    const int rowA = warp_m * 32 + (lane & 15);
    const uint32_t uA = swz(rowA, (lane >> 4) * 16);
    const int rowB = warp_n * 32 + ((lane >> 4) & 1) * 8 + (lane & 7);
    const uint32_t uB = swz(rowB, ((lane >> 3) & 1) * 16);

    auto fill = [&](int s, int koff) {
        const uint32_t ab = sb + s * ST_SZ;
        const uint32_t bb = ab + A_ST;
        CPA16(ab + sA0, gA + (size_t)ra0 * KC + koff + ja0 / 2);
        CPA16(ab + sA1, gA + (size_t)ra1 * KC + koff + ja0 / 2);
        #pragma unroll
        for (int i = 0; i < 4; i++)
            CPA16(bb + sB[i], gB + (size_t)rb[i] * KC + koff + jb[i] / 2);
        asm volatile("cp.async.commit_group;");
    };

    fill(0, 0);
    fill(1, BK);

    const int NKT = KC / BK;   // 8
    int s = 0;
    for (int kt = 0; kt < NKT; kt++) {
        if (kt < NKT - 1) asm volatile("cp.async.wait_group 1;");
        else              asm volatile("cp.async.wait_group 0;");
        __syncthreads();

        if (kt + 2 < NKT) {
            int sn = s + 2; if (sn >= STAGES) sn -= STAGES;
            fill(sn, (kt + 2) * BK);
        }

        const uint32_t abase = sb + s * ST_SZ + uA;
        const uint32_t bbase = sb + s * ST_SZ + A_ST + uB;
        #pragma unroll
        for (int kk = 0; kk < 4; kk++) {
            uint32_t a[2][4], bfr[2][4];
            #pragma unroll
            for (int mi = 0; mi < 2; mi++)
                LDSM4(a[mi][0], a[mi][1], a[mi][2], a[mi][3],
                      (abase + mi * 2048) ^ (kk << 5));
            #pragma unroll
            for (int nb = 0; nb < 2; nb++)
                LDSM4(bfr[nb][0], bfr[nb][1], bfr[nb][2], bfr[nb][3],
                      (bbase + nb * 2048) ^ (kk << 5));
            #pragma unroll
            for (int mi = 0; mi < 2; mi++) {
                MMA16816(c[mi][0], a[mi][0], a[mi][1], a[mi][2], a[mi][3], bfr[0][0], bfr[0][1]);
                MMA16816(c[mi][1], a[mi][0], a[mi][1], a[mi][2], a[mi][3], bfr[0][2], bfr[0][3]);
                MMA16816(c[mi][2], a[mi][0], a[mi][1], a[mi][2], a[mi][3], bfr[1][0], bfr[1][1]);
                MMA16816(c[mi][3], a[mi][0], a[mi][1], a[mi][2], a[mi][3], bfr[1][2], bfr[1][3]);
            }
        }
        if (++s >= STAGES) s -= STAGES;
    }
    __syncthreads();   // smem free for next use
}

// ---------------------------------------------------------------------------
// Fused kernel: split-phase convert, pred GEMM overlapped with enc convert.
// ---------------------------------------------------------------------------
__global__ __launch_bounds__(256, 2)
void fused_kernel(const float* __restrict__ enc_in,
                  const float* __restrict__ pred_in,
                  const float* __restrict__ W,
                  const float* __restrict__ bias,
                  float* __restrict__ out) {
    extern __shared__ __align__(1024) char smem[];
    const uint32_t sb = s2u(smem);
    const int bid = blockIdx.x;
    const int tid = threadIdx.x;
    const int lane = tid & 31;
    const int wid  = tid >> 5;
    const int warp_m = wid & 1;     // 32 M rows
    const int warp_n = wid >> 1;    // 32 N cols

    // ---------- phase 0a: convert pred + W_pred (all 256 blocks) ----------
    {
        const int base = bid * 256 + tid;        // 0..65535
        // pred: 65536 float2 pairs (1/thread)
        {
            float2 x = ((const float2*)pred_in)[base];
            int mm = 1024 + (base >> 8), k2 = (base & 255) * 2;
            *(__half2*)(g_Ac + (size_t)mm * KC + k2) = __floats2half2_rn(x.x, x.y);
        }
        // W_pred half: 524288 pairs (8/thread). W row = 512 pairs; Bp = pairs 256..511.
        #pragma unroll
        for (int j = 0; j < 8; j++) {
            int q = base + j * 65536;            // 0..524287
            int v = q >> 8, kp = q & 255;
            float2 x = ((const float2*)W)[(size_t)v * 512 + 256 + kp];
            *(__half2*)(g_Bp + (size_t)v * KC + kp * 2) = __floats2half2_rn(x.x, x.y);
        }
    }
    __threadfence();
    __syncthreads();
    if (tid == 0) atomicAdd(&g_c1, 1);

    const int m = bid >> 4, n = bid & 15;     // enc tile coords
    const int b = m >> 2;
    const int vbase = n * 128;

    float c[2][4][4];
    const int mrow0 = warp_m * 32 + (lane >> 2);
    const int ncol0 = warp_n * 32 + (lane & 3) * 2;

    if (bid < NDUAL) {
        // ---------- dual blocks: pred GEMM (tile pb=m, n), overlapped ----
        if (tid == 0) wait_cnt(&g_c1, GRID);
        __syncthreads();
        gemm_tile(sb, tid, lane, warp_m, warp_n,
                  g_Ac + (size_t)(1024 + m * 64) * KC,
                  g_Bp + (size_t)(n * 128) * KC, c);
        float* C = g_pred + (size_t)(m * 64) * VOCAB + vbase;
        #pragma unroll
        for (int mi = 0; mi < 2; mi++) {
            #pragma unroll
            for (int ni = 0; ni < 4; ni++) {
                float* p0 = &C[(size_t)(mrow0 + mi * 16)     * VOCAB + ncol0 + ni * 8];
                float* p1 = &C[(size_t)(mrow0 + mi * 16 + 8) * VOCAB + ncol0 + ni * 8];
                *(float2*)p0 = make_float2(c[mi][ni][0], c[mi][ni][1]);
                *(float2*)p1 = make_float2(c[mi][ni][2], c[mi][ni][3]);
            }
        }
        __threadfence();
        __syncthreads();
        if (tid == 0) {
            atomicExch(&g_flags[m * 16 + n], 1);
            wait_cnt(&g_c2, GRID - NDUAL);      // enc/Be images ready?
        }
        __syncthreads();
    } else {
        // ---------- other blocks: phase 0b convert enc + W_enc -----------
        const int lid = bid - NDUAL;             // 0..191
        const int base = lid * 256 + tid;
        #pragma unroll
        for (int j = 0; j < 16; j++) {
            int t = base + j * 49152;            // 0..786431
            if (t < 262144) {                    // enc: 1024 rows x 256 pairs
                float2 x = ((const float2*)enc_in)[t];
                int mm = t >> 8, k2 = (t & 255) * 2;
                *(__half2*)(g_Ac + (size_t)mm * KC + k2) = __floats2half2_rn(x.x, x.y);
            } else {                             // W_enc half: pairs 0..255 per row
                int q = t - 262144;              // 0..524287
                int v = q >> 8, kp = q & 255;
                float2 x = ((const float2*)W)[(size_t)v * 512 + kp];
                *(__half2*)(g_Be + (size_t)v * KC + kp * 2) = __floats2half2_rn(x.x, x.y);
            }
        }
        __threadfence();
        __syncthreads();
        if (tid == 0) {
            atomicAdd(&g_c2, 1);
            wait_cnt(&g_c2, GRID - NDUAL);
        }
        __syncthreads();
    }

    // ---------- enc GEMM: tile (m, n) ----------
    gemm_tile(sb, tid, lane, warp_m, warp_n,
              g_Ac + (size_t)(m * 64) * KC,
              g_Be + (size_t)(n * 128) * KC, c);

    // ---------- enc epilogue: frags -> smem, fetch pred tile, drain ------
    float* enc_s  = (float*)smem;          // [64][PSTR]
    float* pred_s = enc_s + 64 * PSTR;     // [64][PSTR]

    #pragma unroll
    for (int mi = 0; mi < 2; mi++) {
        #pragma unroll
        for (int ni = 0; ni < 4; ni++) {
            float* p0 = &enc_s[(mrow0 + mi * 16)     * PSTR + ncol0 + ni * 8];
            float* p1 = &enc_s[(mrow0 + mi * 16 + 8) * PSTR + ncol0 + ni * 8];
            *(float2*)p0 = make_float2(c[mi][ni][0], c[mi][ni][1]);
            *(float2*)p1 = make_float2(c[mi][ni][2], c[mi][ni][3]);
        }
    }

    if (tid == 0) wait_flag(&g_flags[b * 16 + n]);
    __syncthreads();

    // pred tile + bias -> smem: 64u x 128v = 2048 float4, 8/thread
    {
        const float* pg = g_pred + (size_t)(b * NU) * VOCAB + vbase;
        #pragma unroll
        for (int i = 0; i < 8; i++) {
            int e = tid + i * 256;
            int u = e >> 5, cc = e & 31;
            float4 p = *(const float4*)(pg + (size_t)u * VOCAB + cc * 4);
            float4 bv = *(const float4*)(bias + vbase + cc * 4);
            *(float4*)&pred_s[u * PSTR + cc * 4] =
                make_float4(p.x + bv.x, p.y + bv.y, p.z + bv.z, p.w + bv.w);
        }
    }
    __syncthreads();

    // drain: warp w handles t rows [w*8, w*8+8); per (t,u) row a full warp
    // stores 128 contiguous floats (512B, coalesced). Default (.wb) stores.
    const int col   = lane;
    const int tbase = (m & 3) * 64;
    float* ob = out + ((size_t)(b * NT + tbase) * NU) * VOCAB + vbase;

    #pragma unroll
    for (int ti = 0; ti < 8; ti++) {
        const int t = wid * 8 + ti;
        float4 e = *(float4*)&enc_s[t * PSTR + col * 4];
        float4* orow = (float4*)(ob + (size_t)t * NU * VOCAB);
        #pragma unroll 8
        for (int u = 0; u < NU; u++) {
            float4 p = *(float4*)&pred_s[u * PSTR + col * 4];
            std4(&orow[u * (VOCAB / 4) + col],
                 make_float4(e.x + p.x, e.y + p.y, e.z + p.z, e.w + p.w));
        }
    }

    // ---------- completion + reset (graph-replay correctness) ----------
    __syncthreads();
    if (tid == 0) {
        atomicAdd(&g_done, 1);
        if (bid == 0) {
            wait_cnt(&g_done, GRID);
            #pragma unroll
            for (int i = 0; i < 64; i++) g_flags[i] = 0;
            g_c1 = 0;
            g_c2 = 0;
            g_done = 0;
            __threadfence();
        }
    }
}

// ---------------------------------------------------------------------------
extern "C" void kernel_launch(void* const* d_in, const int* in_sizes, int n_in,
                              void* d_out, int out_size) {
    const float* enc  = (const float*)d_in[0];
    const float* pred = (const float*)d_in[1];
    const float* W    = (const float*)d_in[2];
    const float* bias = (const float*)d_in[3];
    float* out = (float*)d_out;

    cudaFuncSetAttribute(fused_kernel,
                         cudaFuncAttributeMaxDynamicSharedMemorySize, DSMEM);

    fused_kernel<<<GRID, 256, DSMEM>>>(enc, pred, W, bias, out);
}

// round 15
// speedup vs baseline: 1.0231x; 1.0129x over previous
#include <cuda_runtime.h>
#include <cuda_fp16.h>
#include <cstdint>

// RNN-T joint network, ONE launch (grid=256, all co-resident @ occ 2):
//   0a: ALL blocks convert pred + W_pred (fp32->fp16), barrier c1 (256).
//   then: bids 0..63 run pred GEMM 64x128 -> g_pred + flag   (overlapped
//         with) bids 64..255 converting enc + W_enc; barrier c2 (192).
//   all: enc GEMM 64x128 -> smem; wait 1 pred flag (normally pre-set);
//        drain 2MB output brick with coalesced st.global.cs.
//   R15: final config selection — R12 (.cs drain) restored; the write
//        ceiling (~5.8 TB/s, DRAM% ~63) is the platform floor and all
//        tested structural levers are exhausted.
//   end: completion counter; block 0 resets flags/counters (graph replay).

#define VOCAB 2048
#define KC    512
#define NB    4
#define NT    256
#define NU    64
#define GRID  256
#define NDUAL 64

// -------- scratch (device globals; no allocations allowed) --------
__device__ __half g_Ac[1280 * KC];      // enc rows 0..1023, pred rows 1024..1279
__device__ __half g_Be[VOCAB * KC];
__device__ __half g_Bp[VOCAB * KC];
__device__ float  g_pred[256 * VOCAB];
__device__ int    g_flags[64];          // pred tile (pb, n): pb*16 + n
__device__ int    g_c1;                 // 0a barrier (target 256)
__device__ int    g_c2;                 // 0b barrier (target 192)
__device__ int    g_done;               // completion counter (for reset)

// ---------------------------------------------------------------------------
// helpers
// ---------------------------------------------------------------------------
#define BK     64
#define STAGES 3
#define A_ST   8192                   // 64 rows * 128B
#define B_ST   16384                  // 128 rows * 128B
#define ST_SZ  (A_ST + B_ST)          // 24KB per stage
#define DSMEM  (STAGES * ST_SZ)       // 72KB (drain needs 67.6KB <= this)
#define PSTR   132                    // padded fp32 row stride for drain tiles

__device__ __forceinline__ uint32_t s2u(const void* p) {
    return (uint32_t)__cvta_generic_to_shared(p);
}
#define CPA16(s, g) asm volatile("cp.async.cg.shared.global [%0], [%1], 16;" :: "r"(s), "l"(g))
#define LDSM4(r0,r1,r2,r3,a) asm volatile( \
    "ldmatrix.sync.aligned.m8n8.x4.shared.b16 {%0,%1,%2,%3}, [%4];" \
    : "=r"(r0),"=r"(r1),"=r"(r2),"=r"(r3) : "r"(a))
#define MMA16816(c,a0,a1,a2,a3,b0,b1) asm volatile( \
    "mma.sync.aligned.m16n8k16.row.col.f32.f16.f16.f32 " \
    "{%0,%1,%2,%3},{%4,%5,%6,%7},{%8,%9},{%0,%1,%2,%3};" \
    : "+f"(c[0]),"+f"(c[1]),"+f"(c[2]),"+f"(c[3]) \
    : "r"(a0),"r"(a1),"r"(a2),"r"(a3),"r"(b0),"r"(b1))

__device__ __forceinline__ uint32_t swz(uint32_t row, uint32_t cb) {
    return row * 128 + (cb ^ ((row & 7) * 16));
}
__device__ __forceinline__ void stcs(float4* p, float4 v) {
    asm volatile("st.global.cs.v4.f32 [%0], {%1,%2,%3,%4};"
                 :: "l"(p), "f"(v.x), "f"(v.y), "f"(v.z), "f"(v.w));
}
__device__ __forceinline__ void wait_flag(const int* f) {
    int v;
    while (true) {
        asm volatile("ld.acquire.gpu.global.b32 %0, [%1];" : "=r"(v) : "l"(f));
        if (v) break;
        __nanosleep(128);
    }
}
__device__ __forceinline__ void wait_cnt(const int* f, int target) {
    int v;
    while (true) {
        asm volatile("ld.acquire.gpu.global.b32 %0, [%1];" : "=r"(v) : "l"(f));
        if (v == target) break;
        __nanosleep(64);
    }
}

// ---------------------------------------------------------------------------
// one 64x128 fp16 GEMM tile, K=512 (proven R10-R14 mainloop)
// ---------------------------------------------------------------------------
__device__ __forceinline__ void gemm_tile(uint32_t sb, int tid, int lane,
                                          int warp_m, int warp_n,
                                          const __half* __restrict__ gA,
                                          const __half* __restrict__ gB,
                                          float (&c)[2][4][4]) {
    #pragma unroll
    for (int i = 0; i < 2; i++)
        #pragma unroll
        for (int j = 0; j < 4; j++)
            #pragma unroll
            for (int e2 = 0; e2 < 4; e2++) c[i][j][e2] = 0.f;

    const int ra0 = tid >> 3,         ja0 = (tid & 7) * 16;
    const int ra1 = (tid + 256) >> 3;
    const uint32_t sA0 = swz(ra0, ja0), sA1 = swz(ra1, ja0);
    int      rb[4], jb[4];
    uint32_t sB[4];
    #pragma unroll
    for (int i = 0; i < 4; i++) {
        int cidx = tid + i * 256;
        rb[i] = cidx >> 3; jb[i] = (cidx & 7) * 16;
        sB[i] = swz(rb[i], jb[i]);
    }

    const int rowA = warp_m * 32 + (lane & 15);
    const uint32_t uA = swz(rowA, (lane >> 4) * 16);
    const int rowB = warp_n * 32 + ((lane >> 4) & 1) * 8 + (lane & 7);
    const uint32_t uB = swz(rowB, ((lane >> 3) & 1) * 16);

    auto fill = [&](int s, int koff) {
        const uint32_t ab = sb + s * ST_SZ;
        const uint32_t bb = ab + A_ST;
        CPA16(ab + sA0, gA + (size_t)ra0 * KC + koff + ja0 / 2);
        CPA16(ab + sA1, gA + (size_t)ra1 * KC + koff + ja0 / 2);
        #pragma unroll
        for (int i = 0; i < 4; i++)
            CPA16(bb + sB[i], gB + (size_t)rb[i] * KC + koff + jb[i] / 2);
        asm volatile("cp.async.commit_group;");
    };

    fill(0, 0);
    fill(1, BK);

    const int NKT = KC / BK;   // 8
    int s = 0;
    for (int kt = 0; kt < NKT; kt++) {
        if (kt < NKT - 1) asm volatile("cp.async.wait_group 1;");
        else              asm volatile("cp.async.wait_group 0;");
        __syncthreads();

        if (kt + 2 < NKT) {
            int sn = s + 2; if (sn >= STAGES) sn -= STAGES;
            fill(sn, (kt + 2) * BK);
        }

        const uint32_t abase = sb + s * ST_SZ + uA;
        const uint32_t bbase = sb + s * ST_SZ + A_ST + uB;
        #pragma unroll
        for (int kk = 0; kk < 4; kk++) {
            uint32_t a[2][4], bfr[2][4];
            #pragma unroll
            for (int mi = 0; mi < 2; mi++)
                LDSM4(a[mi][0], a[mi][1], a[mi][2], a[mi][3],
                      (abase + mi * 2048) ^ (kk << 5));
            #pragma unroll
            for (int nb = 0; nb < 2; nb++)
                LDSM4(bfr[nb][0], bfr[nb][1], bfr[nb][2], bfr[nb][3],
                      (bbase + nb * 2048) ^ (kk << 5));
            #pragma unroll
            for (int mi = 0; mi < 2; mi++) {
                MMA16816(c[mi][0], a[mi][0], a[mi][1], a[mi][2], a[mi][3], bfr[0][0], bfr[0][1]);
                MMA16816(c[mi][1], a[mi][0], a[mi][1], a[mi][2], a[mi][3], bfr[0][2], bfr[0][3]);
                MMA16816(c[mi][2], a[mi][0], a[mi][1], a[mi][2], a[mi][3], bfr[1][0], bfr[1][1]);
                MMA16816(c[mi][3], a[mi][0], a[mi][1], a[mi][2], a[mi][3], bfr[1][2], bfr[1][3]);
            }
        }
        if (++s >= STAGES) s -= STAGES;
    }
    __syncthreads();   // smem free for next use
}

// ---------------------------------------------------------------------------
// Fused kernel: split-phase convert, pred GEMM overlapped with enc convert.
// ---------------------------------------------------------------------------
__global__ __launch_bounds__(256, 2)
void fused_kernel(const float* __restrict__ enc_in,
                  const float* __restrict__ pred_in,
                  const float* __restrict__ W,
                  const float* __restrict__ bias,
                  float* __restrict__ out) {
    extern __shared__ __align__(1024) char smem[];
    const uint32_t sb = s2u(smem);
    const int bid = blockIdx.x;
    const int tid = threadIdx.x;
    const int lane = tid & 31;
    const int wid  = tid >> 5;
    const int warp_m = wid & 1;     // 32 M rows
    const int warp_n = wid >> 1;    // 32 N cols

    // ---------- phase 0a: convert pred + W_pred (all 256 blocks) ----------
    {
        const int base = bid * 256 + tid;        // 0..65535
        // pred: 65536 float2 pairs (1/thread)
        {
            float2 x = ((const float2*)pred_in)[base];
            int mm = 1024 + (base >> 8), k2 = (base & 255) * 2;
            *(__half2*)(g_Ac + (size_t)mm * KC + k2) = __floats2half2_rn(x.x, x.y);
        }
        // W_pred half: 524288 pairs (8/thread). W row = 512 pairs; Bp = pairs 256..511.
        #pragma unroll
        for (int j = 0; j < 8; j++) {
            int q = base + j * 65536;            // 0..524287
            int v = q >> 8, kp = q & 255;
            float2 x = ((const float2*)W)[(size_t)v * 512 + 256 + kp];
            *(__half2*)(g_Bp + (size_t)v * KC + kp * 2) = __floats2half2_rn(x.x, x.y);
        }
    }
    __threadfence();
    __syncthreads();
    if (tid == 0) atomicAdd(&g_c1, 1);

    const int m = bid >> 4, n = bid & 15;     // enc tile coords
    const int b = m >> 2;
    const int vbase = n * 128;

    float c[2][4][4];
    const int mrow0 = warp_m * 32 + (lane >> 2);
    const int ncol0 = warp_n * 32 + (lane & 3) * 2;

    if (bid < NDUAL) {
        // ---------- dual blocks: pred GEMM (tile pb=m, n), overlapped ----
        if (tid == 0) wait_cnt(&g_c1, GRID);
        __syncthreads();
        gemm_tile(sb, tid, lane, warp_m, warp_n,
                  g_Ac + (size_t)(1024 + m * 64) * KC,
                  g_Bp + (size_t)(n * 128) * KC, c);
        float* C = g_pred + (size_t)(m * 64) * VOCAB + vbase;
        #pragma unroll
        for (int mi = 0; mi < 2; mi++) {
            #pragma unroll
            for (int ni = 0; ni < 4; ni++) {
                float* p0 = &C[(size_t)(mrow0 + mi * 16)     * VOCAB + ncol0 + ni * 8];
                float* p1 = &C[(size_t)(mrow0 + mi * 16 + 8) * VOCAB + ncol0 + ni * 8];
                *(float2*)p0 = make_float2(c[mi][ni][0], c[mi][ni][1]);
                *(float2*)p1 = make_float2(c[mi][ni][2], c[mi][ni][3]);
            }
        }
        __threadfence();
        __syncthreads();
        if (tid == 0) {
            atomicExch(&g_flags[m * 16 + n], 1);
            wait_cnt(&g_c2, GRID - NDUAL);      // enc/Be images ready?
        }
        __syncthreads();
    } else {
        // ---------- other blocks: phase 0b convert enc + W_enc -----------
        const int lid = bid - NDUAL;             // 0..191
        const int base = lid * 256 + tid;
        #pragma unroll
        for (int j = 0; j < 16; j++) {
            int t = base + j * 49152;            // 0..786431
            if (t < 262144) {                    // enc: 1024 rows x 256 pairs
                float2 x = ((const float2*)enc_in)[t];
                int mm = t >> 8, k2 = (t & 255) * 2;
                *(__half2*)(g_Ac + (size_t)mm * KC + k2) = __floats2half2_rn(x.x, x.y);
            } else {                             // W_enc half: pairs 0..255 per row
                int q = t - 262144;              // 0..524287
                int v = q >> 8, kp = q & 255;
                float2 x = ((const float2*)W)[(size_t)v * 512 + kp];
                *(__half2*)(g_Be + (size_t)v * KC + kp * 2) = __floats2half2_rn(x.x, x.y);
            }
        }
        __threadfence();
        __syncthreads();
        if (tid == 0) {
            atomicAdd(&g_c2, 1);
            wait_cnt(&g_c2, GRID - NDUAL);
        }
        __syncthreads();
    }

    // ---------- enc GEMM: tile (m, n) ----------
    gemm_tile(sb, tid, lane, warp_m, warp_n,
              g_Ac + (size_t)(m * 64) * KC,
              g_Be + (size_t)(n * 128) * KC, c);

    // ---------- enc epilogue: frags -> smem, fetch pred tile, drain ------
    float* enc_s  = (float*)smem;          // [64][PSTR]
    float* pred_s = enc_s + 64 * PSTR;     // [64][PSTR]

    #pragma unroll
    for (int mi = 0; mi < 2; mi++) {
        #pragma unroll
        for (int ni = 0; ni < 4; ni++) {
            float* p0 = &enc_s[(mrow0 + mi * 16)     * PSTR + ncol0 + ni * 8];
            float* p1 = &enc_s[(mrow0 + mi * 16 + 8) * PSTR + ncol0 + ni * 8];
            *(float2*)p0 = make_float2(c[mi][ni][0], c[mi][ni][1]);
            *(float2*)p1 = make_float2(c[mi][ni][2], c[mi][ni][3]);
        }
    }

    if (tid == 0) wait_flag(&g_flags[b * 16 + n]);
    __syncthreads();

    // pred tile + bias -> smem: 64u x 128v = 2048 float4, 8/thread
    {
        const float* pg = g_pred + (size_t)(b * NU) * VOCAB + vbase;
        #pragma unroll
        for (int i = 0; i < 8; i++) {
            int e = tid + i * 256;
            int u = e >> 5, cc = e & 31;
            float4 p = *(const float4*)(pg + (size_t)u * VOCAB + cc * 4);
            float4 bv = *(const float4*)(bias + vbase + cc * 4);
            *(float4*)&pred_s[u * PSTR + cc * 4] =
                make_float4(p.x + bv.x, p.y + bv.y, p.z + bv.z, p.w + bv.w);
        }
    }
    __syncthreads();

    // drain: warp w handles t rows [w*8, w*8+8); per (t,u) row a full warp
    // stores 128 contiguous floats (512B, coalesced). Evict-first stores.
    const int col   = lane;
    const int tbase = (m & 3) * 64;
    float* ob = out + ((size_t)(b * NT + tbase) * NU) * VOCAB + vbase;

    #pragma unroll
    for (int ti = 0; ti < 8; ti++) {
        const int t = wid * 8 + ti;
        float4 e = *(float4*)&enc_s[t * PSTR + col * 4];
        float4* orow = (float4*)(ob + (size_t)t * NU * VOCAB);
        #pragma unroll 8
        for (int u = 0; u < NU; u++) {
            float4 p = *(float4*)&pred_s[u * PSTR + col * 4];
            stcs(&orow[u * (VOCAB / 4) + col],
                 make_float4(e.x + p.x, e.y + p.y, e.z + p.z, e.w + p.w));
        }
    }

    // ---------- completion + reset (graph-replay correctness) ----------
    __syncthreads();
    if (tid == 0) {
        atomicAdd(&g_done, 1);
        if (bid == 0) {
            wait_cnt(&g_done, GRID);
            #pragma unroll
            for (int i = 0; i < 64; i++) g_flags[i] = 0;
            g_c1 = 0;
            g_c2 = 0;
            g_done = 0;
            __threadfence();
        }
    }
}

// ---------------------------------------------------------------------------
extern "C" void kernel_launch(void* const* d_in, const int* in_sizes, int n_in,
                              void* d_out, int out_size) {
    const float* enc  = (const float*)d_in[0];
    const float* pred = (const float*)d_in[1];
    const float* W    = (const float*)d_in[2];
    const float* bias = (const float*)d_in[3];
    float* out = (float*)d_out;

    cudaFuncSetAttribute(fused_kernel,
                         cudaFuncAttributeMaxDynamicSharedMemorySize, DSMEM);

    fused_kernel<<<GRID, 256, DSMEM>>>(enc, pred, W, bias, out);
}